// round 1
// baseline (speedup 1.0000x reference)
#include <cuda_runtime.h>
#include <math.h>
#include <stdint.h>

// ---------------------------------------------------------------------------
// ImageEncoderViTSecondHalf: 4 transformer blocks (ws = 14,14,14,global) + neck
// fp32 baseline. Scratch via __device__ globals (no allocation).
// ---------------------------------------------------------------------------

#define TOK 4096          // 64*64 tokens
#define CD 768
#define FD 3072
#define NHD 12
#define HDD 64

__device__ float g_x[TOK * CD];
__device__ float g_xn[TOK * CD];
__device__ float g_qkv[TOK * 3 * CD];
__device__ float g_attn[TOK * CD];
__device__ float g_h[TOK * FD];
__device__ float g_t1[TOK * 256];
__device__ float g_t2[TOK * 256];

// ---------------------------------------------------------------------------
// LayerNorm over 768 channels, one block per row, 256 threads (3 vals each).
// Two-pass (exact match to reference mean((x-m)^2)).
// ---------------------------------------------------------------------------
__global__ __launch_bounds__(256) void ln768_kernel(
    const float* __restrict__ in, const float* __restrict__ g,
    const float* __restrict__ b, float* __restrict__ out, float eps)
{
    int row = blockIdx.x;
    int t = threadIdx.x;
    const float* xp = in + (size_t)row * CD;
    float v0 = xp[t], v1 = xp[t + 256], v2 = xp[t + 512];
    __shared__ float red[256];
    red[t] = v0 + v1 + v2;
    __syncthreads();
#pragma unroll
    for (int off = 128; off > 0; off >>= 1) {
        if (t < off) red[t] += red[t + off];
        __syncthreads();
    }
    float mean = red[0] * (1.0f / 768.0f);
    __syncthreads();
    float d0 = v0 - mean, d1 = v1 - mean, d2 = v2 - mean;
    red[t] = d0 * d0 + d1 * d1 + d2 * d2;
    __syncthreads();
#pragma unroll
    for (int off = 128; off > 0; off >>= 1) {
        if (t < off) red[t] += red[t + off];
        __syncthreads();
    }
    float inv = rsqrtf(red[0] * (1.0f / 768.0f) + eps);
    float* op = out + (size_t)row * CD;
    op[t]       = d0 * inv * g[t]       + b[t];
    op[t + 256] = d1 * inv * g[t + 256] + b[t + 256];
    op[t + 512] = d2 * inv * g[t + 512] + b[t + 512];
}

// ---------------------------------------------------------------------------
// LayerNorm over 256 channels (neck LN2d), one block per pixel.
// transpose=1 writes NCHW output.
// ---------------------------------------------------------------------------
__global__ __launch_bounds__(256) void ln256_kernel(
    const float* __restrict__ in, const float* __restrict__ g,
    const float* __restrict__ b, float* __restrict__ out, float eps, int transpose)
{
    int p = blockIdx.x;
    int c = threadIdx.x;
    float v = in[(size_t)p * 256 + c];
    __shared__ float red[256];
    red[c] = v;
    __syncthreads();
#pragma unroll
    for (int off = 128; off > 0; off >>= 1) {
        if (c < off) red[c] += red[c + off];
        __syncthreads();
    }
    float mean = red[0] * (1.0f / 256.0f);
    __syncthreads();
    float d = v - mean;
    red[c] = d * d;
    __syncthreads();
#pragma unroll
    for (int off = 128; off > 0; off >>= 1) {
        if (c < off) red[c] += red[c + off];
        __syncthreads();
    }
    float inv = rsqrtf(red[0] * (1.0f / 256.0f) + eps);
    float r = d * inv * g[c] + b[c];
    if (transpose)
        out[(size_t)c * TOK + p] = r;
    else
        out[(size_t)p * 256 + c] = r;
}

// ---------------------------------------------------------------------------
// Tiled fp32 GEMM: C[M,N] = A[M,K] @ B[K,N] (+bias, +gelu, +residual)
// 64x64x16 tiles, 256 threads, 4x4 microtile per thread, float4 smem reads.
// M % 64 == 0, N % 64 == 0, K % 16 == 0 (holds for all calls here).
// ---------------------------------------------------------------------------
template<bool GELU, bool HASBIAS, bool HASRES>
__global__ __launch_bounds__(256) void gemm_kernel(
    const float* __restrict__ A, const float* __restrict__ Bm,
    const float* __restrict__ bias, const float* __restrict__ res,
    float* __restrict__ Cm, int M, int N, int K)
{
    __shared__ __align__(16) float As[16][68];   // +4 pad: 2-way store conflict only
    __shared__ __align__(16) float Bs[16][64];
    const int tx = threadIdx.x, ty = threadIdx.y;
    const int tid = ty * 16 + tx;
    const int row0 = blockIdx.y * 64;
    const int col0 = blockIdx.x * 64;
    float acc[4][4];
#pragma unroll
    for (int i = 0; i < 4; i++)
#pragma unroll
        for (int j = 0; j < 4; j++) acc[i][j] = 0.0f;

    for (int k0 = 0; k0 < K; k0 += 16) {
#pragma unroll
        for (int i = 0; i < 4; i++) {
            int idx = tid + i * 256;
            int m = idx >> 4, kk = idx & 15;
            As[kk][m] = A[(size_t)(row0 + m) * K + (k0 + kk)];
            int kb = idx >> 6, nn = idx & 63;
            Bs[kb][nn] = Bm[(size_t)(k0 + kb) * N + (col0 + nn)];
        }
        __syncthreads();
#pragma unroll
        for (int kk = 0; kk < 16; kk++) {
            float4 av = *reinterpret_cast<const float4*>(&As[kk][ty * 4]);
            float4 bv = *reinterpret_cast<const float4*>(&Bs[kk][tx * 4]);
            float a4[4] = {av.x, av.y, av.z, av.w};
            float b4[4] = {bv.x, bv.y, bv.z, bv.w};
#pragma unroll
            for (int i = 0; i < 4; i++)
#pragma unroll
                for (int j = 0; j < 4; j++)
                    acc[i][j] = fmaf(a4[i], b4[j], acc[i][j]);
        }
        __syncthreads();
    }
#pragma unroll
    for (int i = 0; i < 4; i++) {
        int r = row0 + ty * 4 + i;
#pragma unroll
        for (int j = 0; j < 4; j++) {
            int c = col0 + tx * 4 + j;
            float v = acc[i][j];
            if (HASBIAS) v += bias[c];
            if (GELU) v = 0.5f * v * (1.0f + erff(v * 0.70710678118654752f));
            if (HASRES) v += res[(size_t)r * N + c];
            Cm[(size_t)r * N + c] = v;
        }
    }
}

// ---------------------------------------------------------------------------
// Windowed attention (ws=14). Grid (25 windows, 12 heads), 256 threads.
// K/V for the 196 window tokens live in dynamic smem (padded tokens = qkv bias).
// Each thread = 1 query, online softmax, decomposed rel-pos bias.
// ---------------------------------------------------------------------------
#define WIN_SMEM (196 * 64 * 2 * 4)

__global__ __launch_bounds__(256) void win_attn_kernel(
    const float* __restrict__ qkv, const float* __restrict__ qkv_b,
    const float* __restrict__ relH, const float* __restrict__ relW,
    float* __restrict__ out)
{
    extern __shared__ float sm[];
    float* Ks = sm;
    float* Vs = sm + 196 * 64;
    const int win = blockIdx.x, n = blockIdx.y;
    const int wh = (win / 5) * 14, ww = (win % 5) * 14;
    const int tid = threadIdx.x;

    for (int idx = tid; idx < 196 * 64; idx += 256) {
        int r = idx >> 6, d = idx & 63;
        int gh = wh + r / 14, gw = ww + r % 14;
        float kk, vv;
        if (gh < 64 && gw < 64) {
            size_t base = (size_t)(gh * 64 + gw) * 2304 + n * 64 + d;
            kk = qkv[base + 768];
            vv = qkv[base + 1536];
        } else {
            kk = qkv_b[768 + n * 64 + d];
            vv = qkv_b[1536 + n * 64 + d];
        }
        Ks[idx] = kk;
        Vs[idx] = vv;
    }
    __syncthreads();

    if (tid >= 196) return;
    const int qh = tid / 14, qw = tid % 14;
    const int gh = wh + qh, gw = ww + qw;
    if (gh >= 64 || gw >= 64) return;  // padded query: dropped by unpartition
    const int tok = gh * 64 + gw;

    float q[64];
    const float* qp = qkv + (size_t)tok * 2304 + n * 64;
#pragma unroll
    for (int d = 0; d < 64; d++) q[d] = qp[d];

    float rh[14], rw[14];
#pragma unroll 2
    for (int j = 0; j < 14; j++) {
        const float* th = relH + (qh - j + 13) * 64;
        const float* tw = relW + (qw - j + 13) * 64;
        float a = 0.f, c2 = 0.f;
#pragma unroll
        for (int d = 0; d < 64; d++) { a += q[d] * th[d]; c2 += q[d] * tw[d]; }
        rh[j] = a; rw[j] = c2;
    }

    float m = -1e30f, l = 0.0f, o[64];
#pragma unroll
    for (int d = 0; d < 64; d++) o[d] = 0.0f;

    for (int k = 0; k < 196; k++) {
        const float* kv = Ks + k * 64;
        float s = 0.0f;
#pragma unroll
        for (int d = 0; d < 64; d++) s = fmaf(q[d], kv[d], s);
        s = s * 0.125f + rh[k / 14] + rw[k % 14];
        float p;
        if (s > m) {
            float corr = __expf(m - s);
            l *= corr;
#pragma unroll
            for (int d = 0; d < 64; d++) o[d] *= corr;
            m = s;
            p = 1.0f;
        } else {
            p = __expf(s - m);
        }
        l += p;
        const float* vvp = Vs + k * 64;
#pragma unroll
        for (int d = 0; d < 64; d++) o[d] = fmaf(p, vvp[d], o[d]);
    }
    float invl = 1.0f / l;
    float* op = out + (size_t)tok * CD + n * 64;
#pragma unroll
    for (int d = 0; d < 64; d++) op[d] = o[d] * invl;
}

// ---------------------------------------------------------------------------
// Global attention (block 3, 64x64 image = one big window, no padding).
// Grid (32, 12), 128 threads; each thread = 1 query; K/V tiled through smem.
// ---------------------------------------------------------------------------
#define GKT 64

__global__ __launch_bounds__(128) void glob_attn_kernel(
    const float* __restrict__ qkv,
    const float* __restrict__ relH, const float* __restrict__ relW,
    float* __restrict__ out)
{
    __shared__ float Ks[GKT * 64];
    __shared__ float Vs[GKT * 64];
    const int n = blockIdx.y;
    const int tid = threadIdx.x;
    const int qi = blockIdx.x * 128 + tid;
    const int qh = qi >> 6, qw = qi & 63;

    float q[64];
    const float* qp = qkv + (size_t)qi * 2304 + n * 64;
#pragma unroll
    for (int d = 0; d < 64; d++) q[d] = qp[d];

    float rh[64], rw[64];
    for (int j = 0; j < 64; j++) {
        const float* th = relH + (qh - j + 63) * 64;
        const float* tw = relW + (qw - j + 63) * 64;
        float a = 0.f, b2 = 0.f;
#pragma unroll
        for (int d = 0; d < 64; d++) { a += q[d] * th[d]; b2 += q[d] * tw[d]; }
        rh[j] = a; rw[j] = b2;
    }

    float m = -1e30f, l = 0.0f, o[64];
#pragma unroll
    for (int d = 0; d < 64; d++) o[d] = 0.0f;

    for (int kt = 0; kt < TOK; kt += GKT) {
        __syncthreads();
        for (int idx = tid; idx < GKT * 64; idx += 128) {
            int r = idx >> 6, d = idx & 63;
            size_t base = (size_t)(kt + r) * 2304 + n * 64 + d;
            Ks[idx] = qkv[base + 768];
            Vs[idx] = qkv[base + 1536];
        }
        __syncthreads();
        for (int kk = 0; kk < GKT; kk++) {
            int k = kt + kk;
            const float* kv = Ks + kk * 64;
            float s = 0.0f;
#pragma unroll
            for (int d = 0; d < 64; d++) s = fmaf(q[d], kv[d], s);
            s = s * 0.125f + rh[k >> 6] + rw[k & 63];
            float p;
            if (s > m) {
                float corr = __expf(m - s);
                l *= corr;
#pragma unroll
                for (int d = 0; d < 64; d++) o[d] *= corr;
                m = s;
                p = 1.0f;
            } else {
                p = __expf(s - m);
            }
            l += p;
            const float* vvp = Vs + kk * 64;
#pragma unroll
            for (int d = 0; d < 64; d++) o[d] = fmaf(p, vvp[d], o[d]);
        }
    }
    float invl = 1.0f / l;
    float* op = out + (size_t)qi * CD + n * 64;
#pragma unroll
    for (int d = 0; d < 64; d++) op[d] = o[d] * invl;
}

// ---------------------------------------------------------------------------
// Neck 3x3 conv, SAME, NHWC, HWIO weights, C=256->256, no bias.
// One block per (row, 4 consecutive cols); weights streamed from L2,
// 4-pixel reuse per weight load.
// ---------------------------------------------------------------------------
__global__ __launch_bounds__(256) void conv3x3_kernel(
    const float* __restrict__ in, const float* __restrict__ w,
    float* __restrict__ out)
{
    __shared__ float patch[3 * 6 * 256];
    const int y = blockIdx.x >> 4;
    const int x0 = (blockIdx.x & 15) * 4;
    const int tid = threadIdx.x;

    for (int idx = tid; idx < 3 * 6 * 256; idx += 256) {
        int ci = idx & 255;
        int pos = idx >> 8;           // 0..17
        int dy = pos / 6, dx = pos % 6;
        int yy = y + dy - 1, xx = x0 + dx - 1;
        float v = 0.0f;
        if (yy >= 0 && yy < 64 && xx >= 0 && xx < 64)
            v = in[((size_t)(yy * 64 + xx)) * 256 + ci];
        patch[idx] = v;
    }
    __syncthreads();

    const int co = tid;
    float acc0 = 0.f, acc1 = 0.f, acc2 = 0.f, acc3 = 0.f;
#pragma unroll
    for (int dy = 0; dy < 3; dy++) {
#pragma unroll
        for (int dx = 0; dx < 3; dx++) {
            const float* wp = w + ((size_t)(dy * 3 + dx) * 256) * 256 + co;
            const float* pp = patch + (dy * 6 + dx) * 256;
#pragma unroll 4
            for (int ci = 0; ci < 256; ci++) {
                float wv = wp[(size_t)ci * 256];
                acc0 = fmaf(pp[ci], wv, acc0);
                acc1 = fmaf(pp[ci + 256], wv, acc1);
                acc2 = fmaf(pp[ci + 512], wv, acc2);
                acc3 = fmaf(pp[ci + 768], wv, acc3);
            }
        }
    }
    out[((size_t)(y * 64 + x0 + 0)) * 256 + co] = acc0;
    out[((size_t)(y * 64 + x0 + 1)) * 256 + co] = acc1;
    out[((size_t)(y * 64 + x0 + 2)) * 256 + co] = acc2;
    out[((size_t)(y * 64 + x0 + 3)) * 256 + co] = acc3;
}

// ---------------------------------------------------------------------------
// Launch
// ---------------------------------------------------------------------------
extern "C" void kernel_launch(void* const* d_in, const int* in_sizes, int n_in,
                              void* d_out, int out_size)
{
    (void)in_sizes; (void)n_in; (void)out_size;
    const float* x      = (const float*)d_in[0];
    const float* ln1_g  = (const float*)d_in[1];
    const float* ln1_b  = (const float*)d_in[2];
    const float* qkv_w  = (const float*)d_in[3];
    const float* qkv_b  = (const float*)d_in[4];
    const float* proj_w = (const float*)d_in[5];
    const float* proj_b = (const float*)d_in[6];
    const float* rel_h  = (const float*)d_in[7];
    const float* rel_w  = (const float*)d_in[8];
    const float* ln2_g  = (const float*)d_in[9];
    const float* ln2_b  = (const float*)d_in[10];
    const float* fc1_w  = (const float*)d_in[11];
    const float* fc1_b  = (const float*)d_in[12];
    const float* fc2_w  = (const float*)d_in[13];
    const float* fc2_b  = (const float*)d_in[14];
    const float* nc1    = (const float*)d_in[15];
    const float* nl1g   = (const float*)d_in[16];
    const float* nl1b   = (const float*)d_in[17];
    const float* nc2    = (const float*)d_in[18];
    const float* nl2g   = (const float*)d_in[19];
    const float* nl2b   = (const float*)d_in[20];
    float* out = (float*)d_out;

    float *gx, *gxn, *gqkv, *gattn, *gh, *gt1, *gt2;
    cudaGetSymbolAddress((void**)&gx,   g_x);
    cudaGetSymbolAddress((void**)&gxn,  g_xn);
    cudaGetSymbolAddress((void**)&gqkv, g_qkv);
    cudaGetSymbolAddress((void**)&gattn,g_attn);
    cudaGetSymbolAddress((void**)&gh,   g_h);
    cudaGetSymbolAddress((void**)&gt1,  g_t1);
    cudaGetSymbolAddress((void**)&gt2,  g_t2);

    cudaFuncSetAttribute(win_attn_kernel,
                         cudaFuncAttributeMaxDynamicSharedMemorySize, WIN_SMEM);

    cudaMemcpyAsync(gx, x, (size_t)TOK * CD * sizeof(float),
                    cudaMemcpyDeviceToDevice, 0);

    dim3 gb(16, 16);

    for (int b = 0; b < 4; b++) {
        // LN1
        ln768_kernel<<<TOK, 256>>>(gx, ln1_g + b * CD, ln1_b + b * CD, gxn, 1e-5f);
        // QKV GEMM: [4096,768]x[768,2304]
        gemm_kernel<false, true, false><<<dim3(36, 64), gb>>>(
            gxn, qkv_w + (size_t)b * CD * 3 * CD, qkv_b + (size_t)b * 3 * CD,
            nullptr, gqkv, TOK, 3 * CD, CD);
        // Attention
        if (b < 3) {
            win_attn_kernel<<<dim3(25, 12), 256, WIN_SMEM>>>(
                gqkv, qkv_b + (size_t)b * 3 * CD,
                rel_h + (size_t)b * 127 * 64, rel_w + (size_t)b * 127 * 64, gattn);
        } else {
            glob_attn_kernel<<<dim3(32, 12), 128>>>(
                gqkv, rel_h + (size_t)b * 127 * 64, rel_w + (size_t)b * 127 * 64, gattn);
        }
        // Proj GEMM + residual (in-place into gx, safe: 1 thread per element)
        gemm_kernel<false, true, true><<<dim3(12, 64), gb>>>(
            gattn, proj_w + (size_t)b * CD * CD, proj_b + (size_t)b * CD,
            gx, gx, TOK, CD, CD);
        // LN2
        ln768_kernel<<<TOK, 256>>>(gx, ln2_g + b * CD, ln2_b + b * CD, gxn, 1e-5f);
        // FC1 + exact GELU
        gemm_kernel<true, true, false><<<dim3(48, 64), gb>>>(
            gxn, fc1_w + (size_t)b * CD * FD, fc1_b + (size_t)b * FD,
            nullptr, gh, TOK, FD, CD);
        // FC2 + residual
        gemm_kernel<false, true, true><<<dim3(12, 64), gb>>>(
            gh, fc2_w + (size_t)b * FD * CD, fc2_b + (size_t)b * CD,
            gx, gx, TOK, CD, FD);
    }

    // Neck: 1x1 conv (matmul, no bias)
    gemm_kernel<false, false, false><<<dim3(4, 64), gb>>>(
        gx, nc1, nullptr, nullptr, gt1, TOK, 256, CD);
    // LN2d (eps 1e-6)
    ln256_kernel<<<TOK, 256>>>(gt1, nl1g, nl1b, gt2, 1e-6f, 0);
    // 3x3 conv SAME
    conv3x3_kernel<<<1024, 256>>>(gt2, nc2, gt1);
    // LN2d + transpose to NCHW
    ln256_kernel<<<TOK, 256>>>(gt1, nl2g, nl2b, out, 1e-6f, 1);
}